// round 16
// baseline (speedup 1.0000x reference)
#include <cuda_runtime.h>
#include <cuda_bf16.h>
#include <cuda_fp16.h>
#include <cstdint>

#define B_ 8
#define C_ 128
#define O_ 128
#define H_ 64
#define W_ 64
#define HW_ (H_*W_)

// ---------------- scratch ----------------
__device__ __half g_xh[B_*HW_*C_];              // NHWC x, fp16 (8 MB)
__device__ uint4  g_rec[(size_t)B_*HW_*9];      // 16B per (b,hw,tap)
__device__ unsigned char g_wsw[9*32768];        // swizzled fp16 weights [tap][128o x 128c]

// ---------------- helpers ----------------
__device__ __forceinline__ uint32_t smem_u32(const void* p) {
    uint32_t a;
    asm("{ .reg .u64 t; cvta.to.shared.u64 t, %1; cvt.u32.u64 %0, t; }" : "=r"(a) : "l"(p));
    return a;
}
__device__ __forceinline__ void ldsm4(uint32_t& r0, uint32_t& r1, uint32_t& r2, uint32_t& r3,
                                      uint32_t addr) {
    asm volatile("ldmatrix.sync.aligned.m8n8.x4.shared.b16 {%0,%1,%2,%3}, [%4];"
        : "=r"(r0), "=r"(r1), "=r"(r2), "=r"(r3) : "r"(addr));
}
__device__ __forceinline__ void mma16816(float* d, const uint32_t* a, uint32_t b0, uint32_t b1) {
    asm volatile("mma.sync.aligned.m16n8k16.row.col.f32.f16.f16.f32 "
        "{%0,%1,%2,%3}, {%4,%5,%6,%7}, {%8,%9}, {%0,%1,%2,%3};"
        : "+f"(d[0]), "+f"(d[1]), "+f"(d[2]), "+f"(d[3])
        : "r"(a[0]), "r"(a[1]), "r"(a[2]), "r"(a[3]), "r"(b0), "r"(b1));
}
#define CP_ASYNC16(dst, src) \
    asm volatile("cp.async.cg.shared.global [%0], [%1], 16;" :: "r"(dst), "l"(src))
#define CP_COMMIT() asm volatile("cp.async.commit_group;" ::: "memory")
#define CP_WAIT0()  asm volatile("cp.async.wait_group 0;" ::: "memory")

// smem map for k_main (64-px tile, fp16 A): 49 KB -> 4 CTAs/SM (single wave for grid 512)
#define SM_BIAS 0
#define SM_A    1024
#define SM_W    (1024 + 16384)
#define SM_OUT  1024
#define SMEM_MAIN (1024 + 49152)        // 50176 B

// prep: 512 threads/block; offset-conv (fused row transpose) + wprep
#define NB_OFF   512                    // B_*H_
#define NB_WPREP 288                    // 9*128*128 / 512
#define SMEM_PREP (41472 + 16896)       // 58368 B

// ---------------- Fused prep kernel (512 threads) ----------------
__global__ __launch_bounds__(512) void k_prep(
    const float* __restrict__ x, const float* __restrict__ w_off,
    const float* __restrict__ b_off, const float* __restrict__ w_main)
{
    extern __shared__ float smf[];
    int tid = threadIdx.x;
    int bid = blockIdx.x;

    if (bid >= NB_OFF) {
        int idx = (bid - NB_OFF) * 512 + tid;
        int c  = idx & 127;
        int o  = (idx >> 7) & 127;
        int kk = idx >> 14;
        float w = w_main[(o*C_ + c)*9 + kk];
        uint32_t boff = (uint32_t)(o*256 + (((c >> 3) ^ (o & 7)) << 4) + (c & 7)*2);
        *(__half*)(g_wsw + (size_t)kk*32768 + boff) = __float2half_rn(w);
        return;
    }

    float*  ws      = smf;                       // 6*9*128 = 6912 floats
    float*  partial = ws + 6*9*128;              // 64*6*8  = 3072 floats
    float*  off_s   = partial + 64*6*8;          // 64*6    = 384 floats
    __half* xt      = (__half*)(off_s + 384);    // [64px][132ch] fp16 tile

    int b = bid >> 6;
    int h = bid & 63;

    for (int idx = tid; idx < 6*9*128; idx += 512) {
        int c  = idx & 127;
        int m  = (idx >> 7) % 9;
        int dd = idx / (9*128);
        int D  = (dd < 3) ? dd*6 : (dd-3)*2 + 1;
        ws[idx] = w_off[(D*C_ + c)*9 + m];
    }
    __syncthreads();

    int p    = tid & 63;     // pixel (consecutive lanes = consecutive p)
    int q    = tid >> 6;     // channel octant (16 channels each)
    int lane = tid & 31;
    float acc[6] = {0.f, 0.f, 0.f, 0.f, 0.f, 0.f};
    #pragma unroll 2
    for (int c16 = 0; c16 < 16; c16++) {
        int cc = q*16 + c16;
        const float* rowc = x + (size_t)(b*C_ + cc)*HW_;
        #pragma unroll
        for (int i = 0; i < 3; i++) {
            int y = h - 1 + i;
            if ((unsigned)y < (unsigned)H_) {
                const float* row = rowc + y*W_;
                // one LDG per lane; neighbors via warp shuffle (edge lanes reload)
                float x0  = row[p];
                float xm1 = __shfl_up_sync(0xffffffffu, x0, 1);
                if (lane == 0)  xm1 = (p > 0)      ? row[p-1] : 0.f;
                float xp1 = __shfl_down_sync(0xffffffffu, x0, 1);
                if (lane == 31) xp1 = (p < W_-1)   ? row[p+1] : 0.f;
                if (i == 1)
                    xt[p*132 + cc] = __float2half_rn(x0);
                #pragma unroll
                for (int d = 0; d < 6; d++) {
                    const float* wsd = ws + (d*9 + i*3)*128 + cc;
                    acc[d] = fmaf(xm1, wsd[0],   acc[d]);
                    acc[d] = fmaf(x0,  wsd[128], acc[d]);
                    acc[d] = fmaf(xp1, wsd[256], acc[d]);
                }
            }
        }
    }
    #pragma unroll
    for (int d = 0; d < 6; d++)
        partial[(p*6 + d)*8 + q] = acc[d];
    __syncthreads();

    for (int idx = tid; idx < 384; idx += 512) {
        int pp = idx / 6, d = idx % 6;
        int D = (d < 3) ? d*6 : (d-3)*2 + 1;
        float v = b_off[D];
        #pragma unroll
        for (int qq = 0; qq < 8; qq++) v += partial[(pp*6 + d)*8 + qq];
        off_s[pp*6 + d] = v;
    }
    {
        __half* dstrow = g_xh + (size_t)(b*H_ + h)*W_*C_;
        for (int idx = tid; idx < 2048; idx += 512) {
            int px = idx >> 5, u = idx & 31;
            ((uint2*)(dstrow + px*C_))[u] = ((const uint2*)(xt + px*132))[u];
        }
    }
    __syncthreads();
    if (tid < 64) {
        int pp = tid;
        float oxs[3], oys[3];
        oxs[0] = off_s[pp*6 + 0];
        oxs[1] = oxs[0] + off_s[pp*6 + 1];
        oxs[2] = oxs[1] + off_s[pp*6 + 2];
        oys[0] = off_s[pp*6 + 3];
        oys[1] = oys[0] + off_s[pp*6 + 4];
        oys[2] = oys[1] + off_s[pp*6 + 5];
        float xg = pp * (2.0f/63.0f) - 1.0f;
        float yg = h  * (2.0f/63.0f) - 1.0f;
        uint4* dst = g_rec + (size_t)((b*H_ + h)*W_ + pp)*9;
        #pragma unroll
        for (int i = 0; i < 3; i++) {
            #pragma unroll
            for (int j = 0; j < 3; j++) {
                float gx = (xg + oxs[i] + 1.0f)*(W_*0.5f) - 0.5f;
                float gy = (yg + oys[j] + 1.0f)*(H_*0.5f) - 0.5f;
                float x0f = floorf(gx), y0f = floorf(gy);
                int ix = (int)x0f, iy = (int)y0f;
                float wx = gx - x0f, wy = gy - y0f;
                float w00 = (1.f-wx)*(1.f-wy), w01 = wx*(1.f-wy);
                float w10 = (1.f-wx)*wy,       w11 = wx*wy;
                bool vx0 = (unsigned)ix < (unsigned)W_, vx1 = (unsigned)(ix+1) < (unsigned)W_;
                bool vy0 = (unsigned)iy < (unsigned)H_, vy1 = (unsigned)(iy+1) < (unsigned)H_;
                w00 = (vx0 && vy0) ? w00 : 0.f;
                w01 = (vx1 && vy0) ? w01 : 0.f;
                w10 = (vx0 && vy1) ? w10 : 0.f;
                w11 = (vx1 && vy1) ? w11 : 0.f;
                int cx0 = min(max(ix,   0), W_-1), cx1 = min(max(ix+1, 0), W_-1);
                int cy0 = min(max(iy,   0), H_-1), cy1 = min(max(iy+1, 0), H_-1);
                __half2 wa = __floats2half2_rn(w00, w01);
                __half2 wb = __floats2half2_rn(w10, w11);
                uint4 r;
                r.x = *reinterpret_cast<uint32_t*>(&wa);
                r.y = *reinterpret_cast<uint32_t*>(&wb);
                r.z = (uint32_t)(cy0*W_ + cx0) | ((uint32_t)(cy0*W_ + cx1) << 16);
                r.w = (uint32_t)(cy1*W_ + cx0) | ((uint32_t)(cy1*W_ + cx1) << 16);
                dst[i*3 + j] = r;
            }
        }
    }
}

// ---------------- Kernel C: fp16 gather + mma.sync fp16 GEMM ----------------
// 4 CTAs/SM -> all 512 CTAs resident in ONE wave. (Unchanged from R15.)
__global__ __launch_bounds__(256,4) void k_main(
    const float* __restrict__ b_main, float* __restrict__ out)
{
    extern __shared__ char smc[];
    uint32_t sb = smem_u32(smc);
    int tid = threadIdx.x;
    int wid = tid >> 5, lane = tid & 31;

    int bid = blockIdx.x;
    int b   = bid >> 6;
    int hw0 = (bid & 63) << 6;
    const uint2* xb2 = (const uint2*)(g_xh + (size_t)b*HW_*C_);

    if (tid < 128) *(float*)(smc + SM_BIAS + tid*4) = b_main[tid];

    int m0 = (wid & 1) << 5;     // 2 m-warps of 32 px
    int o0 = (wid >> 1) << 5;    // 4 n-warps of 32 outputs

    int l7   = lane & 7;
    int arow = l7 + ((lane >> 3) & 1) * 8;
    int au   = lane >> 4;
    int brow = l7 + (lane >> 4) * 8;
    int bu   = (lane >> 3) & 1;

    float acc[32];
    #pragma unroll
    for (int i = 0; i < 32; i++) acc[i] = 0.f;

    for (int kk = 0; kk < 9; kk++) {
        __syncthreads();   // prev tap's ldsm reads done; A/W writable

        // cp.async this tap's fp16 weights (32 KB)
        {
            const char* wg = (const char*)(g_wsw + (size_t)kk*32768);
            uint32_t dw = sb + SM_W + tid*16;
            #pragma unroll
            for (int i = 0; i < 8; i++)
                CP_ASYNC16(dw + i*4096, wg + i*4096 + tid*16);
            CP_COMMIT();
        }

        // sample 8 px per warp; lane owns 4 channels; fp16 bilinear via HFMA2
        const uint4* recbase = g_rec + (size_t)(b*HW_ + hw0)*9 + kk;
        #pragma unroll 2
        for (int p = wid*8; p < wid*8 + 8; p++) {
            uint4 rec = recbase[(size_t)p*9];
            __half2 wa = *reinterpret_cast<__half2*>(&rec.x);   // {w00, w01}
            __half2 wb = *reinterpret_cast<__half2*>(&rec.y);   // {w10, w11}
            __half2 w00 = __low2half2(wa),  w01 = __high2half2(wa);
            __half2 w10 = __low2half2(wb),  w11 = __high2half2(wb);
            uint2 a00 = xb2[((rec.z & 0xFFFFu) << 5) + lane];
            uint2 a01 = xb2[((rec.z >> 16)     << 5) + lane];
            uint2 a10 = xb2[((rec.w & 0xFFFFu) << 5) + lane];
            uint2 a11 = xb2[((rec.w >> 16)     << 5) + lane];
            __half2 v01 = __hmul2(*reinterpret_cast<__half2*>(&a00.x), w00);
            __half2 v23 = __hmul2(*reinterpret_cast<__half2*>(&a00.y), w00);
            v01 = __hfma2(*reinterpret_cast<__half2*>(&a01.x), w01, v01);
            v23 = __hfma2(*reinterpret_cast<__half2*>(&a01.y), w01, v23);
            v01 = __hfma2(*reinterpret_cast<__half2*>(&a10.x), w10, v01);
            v23 = __hfma2(*reinterpret_cast<__half2*>(&a10.y), w10, v23);
            v01 = __hfma2(*reinterpret_cast<__half2*>(&a11.x), w11, v01);
            v23 = __hfma2(*reinterpret_cast<__half2*>(&a11.y), w11, v23);
            uint2 hp;
            hp.x = *reinterpret_cast<uint32_t*>(&v01);
            hp.y = *reinterpret_cast<uint32_t*>(&v23);
            uint32_t boff = (uint32_t)(p*256 + (((lane >> 1) ^ (p & 7)) << 4) + (lane & 1)*8);
            *(uint2*)(smc + SM_A + boff) = hp;
        }
        CP_WAIT0();
        __syncthreads();   // A + W tiles ready

        // ---- MMA over 8 k16 steps (8 HMMA/step) ----
        #pragma unroll 2
        for (int step = 0; step < 8; step++) {
            int u0 = step << 1;
            uint32_t ah[2][4];
            #pragma unroll
            for (int mt = 0; mt < 2; mt++) {
                uint32_t aoff = (uint32_t)((m0 + mt*16 + arow)*256 + (((u0 + au) ^ l7) << 4));
                ldsm4(ah[mt][0], ah[mt][1], ah[mt][2], ah[mt][3], sb + SM_A + aoff);
            }
            #pragma unroll
            for (int np = 0; np < 2; np++) {
                uint32_t boff = (uint32_t)((o0 + np*16 + brow)*256 + (((u0 + bu) ^ l7) << 4));
                uint32_t bh0, bh1, bh2, bh3;
                ldsm4(bh0, bh1, bh2, bh3, sb + SM_W + boff);
                #pragma unroll
                for (int mt = 0; mt < 2; mt++) {
                    float* d0 = &acc[(mt*4 + np*2    )*4];
                    float* d1 = &acc[(mt*4 + np*2 + 1)*4];
                    mma16816(d0, ah[mt], bh0, bh1);
                    mma16816(d1, ah[mt], bh2, bh3);
                }
            }
        }
    }

    // ---- epilogue: two half passes staged at SM_OUT (stride 66), coalesced STG ----
    const float* bias = (const float*)(smc + SM_BIAS);
    float* outs = (float*)(smc + SM_OUT);
    #pragma unroll
    for (int half = 0; half < 2; half++) {
        __syncthreads();
        if ((o0 >> 6) == half) {
            int ob = o0 & 63;
            #pragma unroll
            for (int mt = 0; mt < 2; mt++) {
                #pragma unroll
                for (int nt = 0; nt < 4; nt++) {
                    float* d = &acc[(mt*4 + nt)*4];
                    int r = m0 + mt*16 + (lane >> 2);
                    int o = ob + nt*8 + (lane & 3)*2;
                    outs[ o     *66 + r    ] = d[0];
                    outs[(o + 1)*66 + r    ] = d[1];
                    outs[ o     *66 + r + 8] = d[2];
                    outs[(o + 1)*66 + r + 8] = d[3];
                }
            }
        }
        __syncthreads();
        for (int idx = tid; idx < 64*64; idx += 256) {
            int o = half*64 + (idx >> 6);
            int px = idx & 63;
            out[(size_t)(b*O_ + o)*HW_ + hw0 + px] = outs[(o & 63)*66 + px] + bias[o];
        }
    }
}

// ---------------- launch ----------------
extern "C" void kernel_launch(void* const* d_in, const int* in_sizes, int n_in,
                              void* d_out, int out_size) {
    const float* x      = (const float*)d_in[0];
    const float* w_off  = (const float*)d_in[1];
    const float* b_off  = (const float*)d_in[2];
    const float* w_main = (const float*)d_in[3];
    const float* b_main = (const float*)d_in[4];
    float* out = (float*)d_out;

    cudaFuncSetAttribute(k_prep, cudaFuncAttributeMaxDynamicSharedMemorySize, SMEM_PREP);
    cudaFuncSetAttribute(k_main, cudaFuncAttributeMaxDynamicSharedMemorySize, SMEM_MAIN);

    k_prep<<<NB_OFF + NB_WPREP, 512, SMEM_PREP>>>(x, w_off, b_off, w_main);
    k_main<<<B_*HW_/64, 256, SMEM_MAIN>>>(b_main, out);
}

// round 17
// speedup vs baseline: 1.0532x; 1.0532x over previous
#include <cuda_runtime.h>
#include <cuda_bf16.h>
#include <cuda_fp16.h>
#include <cstdint>

#define B_ 8
#define C_ 128
#define O_ 128
#define H_ 64
#define W_ 64
#define HW_ (H_*W_)

// ---------------- scratch ----------------
__device__ __half g_xh[B_*HW_*C_];              // NHWC x, fp16 (8 MB)
__device__ uint4  g_rec[(size_t)B_*HW_*9];      // 16B per (b,hw,tap)
__device__ unsigned char g_wsw[9*32768];        // swizzled fp16 weights [tap][128o x 128c]

// ---------------- helpers ----------------
__device__ __forceinline__ uint32_t smem_u32(const void* p) {
    uint32_t a;
    asm("{ .reg .u64 t; cvta.to.shared.u64 t, %1; cvt.u32.u64 %0, t; }" : "=r"(a) : "l"(p));
    return a;
}
__device__ __forceinline__ void ldsm4(uint32_t& r0, uint32_t& r1, uint32_t& r2, uint32_t& r3,
                                      uint32_t addr) {
    asm volatile("ldmatrix.sync.aligned.m8n8.x4.shared.b16 {%0,%1,%2,%3}, [%4];"
        : "=r"(r0), "=r"(r1), "=r"(r2), "=r"(r3) : "r"(addr));
}
__device__ __forceinline__ void mma16816(float* d, const uint32_t* a, uint32_t b0, uint32_t b1) {
    asm volatile("mma.sync.aligned.m16n8k16.row.col.f32.f16.f16.f32 "
        "{%0,%1,%2,%3}, {%4,%5,%6,%7}, {%8,%9}, {%0,%1,%2,%3};"
        : "+f"(d[0]), "+f"(d[1]), "+f"(d[2]), "+f"(d[3])
        : "r"(a[0]), "r"(a[1]), "r"(a[2]), "r"(a[3]), "r"(b0), "r"(b1));
}
#define CP_ASYNC16(dst, src) \
    asm volatile("cp.async.cg.shared.global [%0], [%1], 16;" :: "r"(dst), "l"(src))
#define CP_COMMIT() asm volatile("cp.async.commit_group;" ::: "memory")
#define CP_WAIT0()  asm volatile("cp.async.wait_group 0;" ::: "memory")

// smem map for k_main (128-px tile, 512 threads, 2 CTAs/SM, single wave for grid 256)
#define SM_BIAS 0
#define SM_A    1024
#define SM_W    (1024 + 32768)
#define SM_OUT  1024
#define SMEM_MAIN (1024 + 65536)        // 66560 B

// prep: 512 threads/block; offset-conv (fused row transpose) + wprep  (R15 version)
#define NB_OFF   512                    // B_*H_
#define NB_WPREP 288                    // 9*128*128 / 512
#define SMEM_PREP (41472 + 16896)       // 58368 B

// ---------------- Fused prep kernel (512 threads, R15) ----------------
__global__ __launch_bounds__(512) void k_prep(
    const float* __restrict__ x, const float* __restrict__ w_off,
    const float* __restrict__ b_off, const float* __restrict__ w_main)
{
    extern __shared__ float smf[];
    int tid = threadIdx.x;
    int bid = blockIdx.x;

    if (bid >= NB_OFF) {
        int idx = (bid - NB_OFF) * 512 + tid;
        int c  = idx & 127;
        int o  = (idx >> 7) & 127;
        int kk = idx >> 14;
        float w = w_main[(o*C_ + c)*9 + kk];
        uint32_t boff = (uint32_t)(o*256 + (((c >> 3) ^ (o & 7)) << 4) + (c & 7)*2);
        *(__half*)(g_wsw + (size_t)kk*32768 + boff) = __float2half_rn(w);
        return;
    }

    float*  ws      = smf;                       // 6*9*128 = 6912 floats
    float*  partial = ws + 6*9*128;              // 64*6*8  = 3072 floats
    float*  off_s   = partial + 64*6*8;          // 64*6    = 384 floats
    __half* xt      = (__half*)(off_s + 384);    // [64px][132ch] fp16 tile

    int b = bid >> 6;
    int h = bid & 63;

    for (int idx = tid; idx < 6*9*128; idx += 512) {
        int c  = idx & 127;
        int m  = (idx >> 7) % 9;
        int dd = idx / (9*128);
        int D  = (dd < 3) ? dd*6 : (dd-3)*2 + 1;
        ws[idx] = w_off[(D*C_ + c)*9 + m];
    }
    __syncthreads();

    int p = tid & 63;
    int q = tid >> 6;
    float acc[6] = {0.f, 0.f, 0.f, 0.f, 0.f, 0.f};
    #pragma unroll 2
    for (int c16 = 0; c16 < 16; c16++) {
        int cc = q*16 + c16;
        const float* rowc = x + (size_t)(b*C_ + cc)*HW_;
        #pragma unroll
        for (int i = 0; i < 3; i++) {
            int y = h - 1 + i;
            if ((unsigned)y < (unsigned)H_) {
                const float* row = rowc + y*W_;
                float xm1 = (p > 0)      ? row[p-1] : 0.f;
                float x0  =               row[p];
                float xp1 = (p < W_-1)   ? row[p+1] : 0.f;
                if (i == 1)
                    xt[p*132 + cc] = __float2half_rn(x0);
                #pragma unroll
                for (int d = 0; d < 6; d++) {
                    const float* wsd = ws + (d*9 + i*3)*128 + cc;
                    acc[d] = fmaf(xm1, wsd[0],   acc[d]);
                    acc[d] = fmaf(x0,  wsd[128], acc[d]);
                    acc[d] = fmaf(xp1, wsd[256], acc[d]);
                }
            }
        }
    }
    #pragma unroll
    for (int d = 0; d < 6; d++)
        partial[(p*6 + d)*8 + q] = acc[d];
    __syncthreads();

    for (int idx = tid; idx < 384; idx += 512) {
        int pp = idx / 6, d = idx % 6;
        int D = (d < 3) ? d*6 : (d-3)*2 + 1;
        float v = b_off[D];
        #pragma unroll
        for (int qq = 0; qq < 8; qq++) v += partial[(pp*6 + d)*8 + qq];
        off_s[pp*6 + d] = v;
    }
    {
        __half* dstrow = g_xh + (size_t)(b*H_ + h)*W_*C_;
        for (int idx = tid; idx < 2048; idx += 512) {
            int px = idx >> 5, u = idx & 31;
            ((uint2*)(dstrow + px*C_))[u] = ((const uint2*)(xt + px*132))[u];
        }
    }
    __syncthreads();
    if (tid < 64) {
        int pp = tid;
        float oxs[3], oys[3];
        oxs[0] = off_s[pp*6 + 0];
        oxs[1] = oxs[0] + off_s[pp*6 + 1];
        oxs[2] = oxs[1] + off_s[pp*6 + 2];
        oys[0] = off_s[pp*6 + 3];
        oys[1] = oys[0] + off_s[pp*6 + 4];
        oys[2] = oys[1] + off_s[pp*6 + 5];
        float xg = pp * (2.0f/63.0f) - 1.0f;
        float yg = h  * (2.0f/63.0f) - 1.0f;
        uint4* dst = g_rec + (size_t)((b*H_ + h)*W_ + pp)*9;
        #pragma unroll
        for (int i = 0; i < 3; i++) {
            #pragma unroll
            for (int j = 0; j < 3; j++) {
                float gx = (xg + oxs[i] + 1.0f)*(W_*0.5f) - 0.5f;
                float gy = (yg + oys[j] + 1.0f)*(H_*0.5f) - 0.5f;
                float x0f = floorf(gx), y0f = floorf(gy);
                int ix = (int)x0f, iy = (int)y0f;
                float wx = gx - x0f, wy = gy - y0f;
                float w00 = (1.f-wx)*(1.f-wy), w01 = wx*(1.f-wy);
                float w10 = (1.f-wx)*wy,       w11 = wx*wy;
                bool vx0 = (unsigned)ix < (unsigned)W_, vx1 = (unsigned)(ix+1) < (unsigned)W_;
                bool vy0 = (unsigned)iy < (unsigned)H_, vy1 = (unsigned)(iy+1) < (unsigned)H_;
                w00 = (vx0 && vy0) ? w00 : 0.f;
                w01 = (vx1 && vy0) ? w01 : 0.f;
                w10 = (vx0 && vy1) ? w10 : 0.f;
                w11 = (vx1 && vy1) ? w11 : 0.f;
                int cx0 = min(max(ix,   0), W_-1), cx1 = min(max(ix+1, 0), W_-1);
                int cy0 = min(max(iy,   0), H_-1), cy1 = min(max(iy+1, 0), H_-1);
                __half2 wa = __floats2half2_rn(w00, w01);
                __half2 wb = __floats2half2_rn(w10, w11);
                uint4 r;
                r.x = *reinterpret_cast<uint32_t*>(&wa);
                r.y = *reinterpret_cast<uint32_t*>(&wb);
                r.z = (uint32_t)(cy0*W_ + cx0) | ((uint32_t)(cy0*W_ + cx1) << 16);
                r.w = (uint32_t)(cy1*W_ + cx0) | ((uint32_t)(cy1*W_ + cx1) << 16);
                dst[i*3 + j] = r;
            }
        }
    }
}

// ---------------- Kernel C: 128px x 128o, 512 threads, 2 CTAs/SM (single wave) ----------------
// 16 warps = 4m x 4n, warp tile 32x32. W cp.async amortized over 2x pixels.
__global__ __launch_bounds__(512,2) void k_main(
    const float* __restrict__ b_main, float* __restrict__ out)
{
    extern __shared__ char smc[];
    uint32_t sb = smem_u32(smc);
    int tid = threadIdx.x;
    int wid = tid >> 5, lane = tid & 31;

    int bid = blockIdx.x;
    int b   = bid >> 5;
    int hw0 = (bid & 31) << 7;
    const uint2* xb2 = (const uint2*)(g_xh + (size_t)b*HW_*C_);

    if (tid < 128) *(float*)(smc + SM_BIAS + tid*4) = b_main[tid];

    int m0 = (wid & 3) << 5;     // 4 m-warps of 32 px
    int o0 = (wid >> 2) << 5;    // 4 n-warps of 32 outputs

    int l7   = lane & 7;
    int arow = l7 + ((lane >> 3) & 1) * 8;
    int au   = lane >> 4;
    int brow = l7 + (lane >> 4) * 8;
    int bu   = (lane >> 3) & 1;

    float acc[32];
    #pragma unroll
    for (int i = 0; i < 32; i++) acc[i] = 0.f;

    for (int kk = 0; kk < 9; kk++) {
        __syncthreads();   // prev tap's ldsm reads done; A/W writable

        // cp.async this tap's fp16 weights (32 KB, 512 threads -> 4 rounds)
        {
            const char* wg = (const char*)(g_wsw + (size_t)kk*32768);
            uint32_t dw = sb + SM_W + tid*16;
            #pragma unroll
            for (int i = 0; i < 4; i++)
                CP_ASYNC16(dw + i*8192, wg + i*8192 + tid*16);
            CP_COMMIT();
        }

        // sample 8 px per warp (16 warps x 8 = 128 px); fp16 bilinear via HFMA2
        const uint4* recbase = g_rec + (size_t)(b*HW_ + hw0)*9 + kk;
        #pragma unroll 2
        for (int p = wid*8; p < wid*8 + 8; p++) {
            uint4 rec = recbase[(size_t)p*9];
            __half2 wa = *reinterpret_cast<__half2*>(&rec.x);   // {w00, w01}
            __half2 wb = *reinterpret_cast<__half2*>(&rec.y);   // {w10, w11}
            __half2 w00 = __low2half2(wa),  w01 = __high2half2(wa);
            __half2 w10 = __low2half2(wb),  w11 = __high2half2(wb);
            uint2 a00 = xb2[((rec.z & 0xFFFFu) << 5) + lane];
            uint2 a01 = xb2[((rec.z >> 16)     << 5) + lane];
            uint2 a10 = xb2[((rec.w & 0xFFFFu) << 5) + lane];
            uint2 a11 = xb2[((rec.w >> 16)     << 5) + lane];
            __half2 v01 = __hmul2(*reinterpret_cast<__half2*>(&a00.x), w00);
            __half2 v23 = __hmul2(*reinterpret_cast<__half2*>(&a00.y), w00);
            v01 = __hfma2(*reinterpret_cast<__half2*>(&a01.x), w01, v01);
            v23 = __hfma2(*reinterpret_cast<__half2*>(&a01.y), w01, v23);
            v01 = __hfma2(*reinterpret_cast<__half2*>(&a10.x), w10, v01);
            v23 = __hfma2(*reinterpret_cast<__half2*>(&a10.y), w10, v23);
            v01 = __hfma2(*reinterpret_cast<__half2*>(&a11.x), w11, v01);
            v23 = __hfma2(*reinterpret_cast<__half2*>(&a11.y), w11, v23);
            uint2 hp;
            hp.x = *reinterpret_cast<uint32_t*>(&v01);
            hp.y = *reinterpret_cast<uint32_t*>(&v23);
            uint32_t boff = (uint32_t)(p*256 + (((lane >> 1) ^ (p & 7)) << 4) + (lane & 1)*8);
            *(uint2*)(smc + SM_A + boff) = hp;
        }
        CP_WAIT0();
        __syncthreads();   // A + W tiles ready

        // ---- MMA over 8 k16 steps (8 HMMA/step per warp) ----
        #pragma unroll 2
        for (int step = 0; step < 8; step++) {
            int u0 = step << 1;
            uint32_t ah[2][4];
            #pragma unroll
            for (int mt = 0; mt < 2; mt++) {
                uint32_t aoff = (uint32_t)((m0 + mt*16 + arow)*256 + (((u0 + au) ^ l7) << 4));
                ldsm4(ah[mt][0], ah[mt][1], ah[mt][2], ah[mt][3], sb + SM_A + aoff);
            }
            #pragma unroll
            for (int np = 0; np < 2; np++) {
                uint32_t boff = (uint32_t)((o0 + np*16 + brow)*256 + (((u0 + bu) ^ l7) << 4));
                uint32_t bh0, bh1, bh2, bh3;
                ldsm4(bh0, bh1, bh2, bh3, sb + SM_W + boff);
                #pragma unroll
                for (int mt = 0; mt < 2; mt++) {
                    float* d0 = &acc[(mt*4 + np*2    )*4];
                    float* d1 = &acc[(mt*4 + np*2 + 1)*4];
                    mma16816(d0, ah[mt], bh0, bh1);
                    mma16816(d1, ah[mt], bh2, bh3);
                }
            }
        }
    }

    // ---- epilogue: two half passes over o, staged at SM_OUT (stride 132), 512B STG rows ----
    const float* bias = (const float*)(smc + SM_BIAS);
    float* outs = (float*)(smc + SM_OUT);
    #pragma unroll
    for (int half = 0; half < 2; half++) {
        __syncthreads();
        if ((o0 >> 6) == half) {
            int ob = o0 & 63;
            #pragma unroll
            for (int mt = 0; mt < 2; mt++) {
                #pragma unroll
                for (int nt = 0; nt < 4; nt++) {
                    float* d = &acc[(mt*4 + nt)*4];
                    int r = m0 + mt*16 + (lane >> 2);
                    int o = ob + nt*8 + (lane & 3)*2;
                    outs[ o     *132 + r    ] = d[0];
                    outs[(o + 1)*132 + r    ] = d[1];
                    outs[ o     *132 + r + 8] = d[2];
                    outs[(o + 1)*132 + r + 8] = d[3];
                }
            }
        }
        __syncthreads();
        for (int idx = tid; idx < 64*128; idx += 512) {
            int o = half*64 + (idx >> 7);
            int px = idx & 127;
            out[(size_t)(b*O_ + o)*HW_ + hw0 + px] = outs[(o & 63)*132 + px] + bias[o];
        }
    }
}

// ---------------- launch ----------------
extern "C" void kernel_launch(void* const* d_in, const int* in_sizes, int n_in,
                              void* d_out, int out_size) {
    const float* x      = (const float*)d_in[0];
    const float* w_off  = (const float*)d_in[1];
    const float* b_off  = (const float*)d_in[2];
    const float* w_main = (const float*)d_in[3];
    const float* b_main = (const float*)d_in[4];
    float* out = (float*)d_out;

    cudaFuncSetAttribute(k_prep, cudaFuncAttributeMaxDynamicSharedMemorySize, SMEM_PREP);
    cudaFuncSetAttribute(k_main, cudaFuncAttributeMaxDynamicSharedMemorySize, SMEM_MAIN);

    k_prep<<<NB_OFF + NB_WPREP, 512, SMEM_PREP>>>(x, w_off, b_off, w_main);
    k_main<<<B_*HW_/128, 512, SMEM_MAIN>>>(b_main, out);
}